// round 5
// baseline (speedup 1.0000x reference)
#include <cuda_runtime.h>

#define G3 (64 * 64 * 64)          // 262144 voxels per batch
#define QUADS_PER_B (G3 / 4)       // 65536 voxel quads per batch

typedef unsigned long long u64;

__device__ __forceinline__ u64 f2fma(u64 a, u64 b, u64 c) {
    u64 d; asm("fma.rn.f32x2 %0, %1, %2, %3;" : "=l"(d) : "l"(a), "l"(b), "l"(c)); return d;
}
__device__ __forceinline__ u64 f2mul(u64 a, u64 b) {
    u64 d; asm("mul.rn.f32x2 %0, %1, %2;" : "=l"(d) : "l"(a), "l"(b)); return d;
}
__device__ __forceinline__ u64 f2dup(float x) {
    u64 d; asm("mov.b64 %0, {%1, %1};" : "=l"(d) : "f"(x)); return d;
}

// Quad value: 4 voxels = two f32x2 lanes. 16B-aligned so stores are STG.128.
struct __align__(16) Q { u64 x, y; };

__device__ __forceinline__ Q qfma(Q a, Q b, Q c) {
    Q r; r.x = f2fma(a.x, b.x, c.x); r.y = f2fma(a.y, b.y, c.y); return r;
}
__device__ __forceinline__ Q qmul(Q a, Q b) {
    Q r; r.x = f2mul(a.x, b.x); r.y = f2mul(a.y, b.y); return r;
}
// broadcast c0 operand (same u64 pair for both lanes)
__device__ __forceinline__ Q qfmac(Q a, u64 c0, Q c) {
    Q r; r.x = f2fma(a.x, c0, c.x); r.y = f2fma(a.y, c0, c.y); return r;
}
__device__ __forceinline__ Q qmulc(Q a, u64 c0) {
    Q r; r.x = f2mul(a.x, c0); r.y = f2mul(a.y, c0); return r;
}

// One thread = 4 consecutive voxels. Voxel index is innermost in every tensor,
// so alpha loads are LDG.128 and all 81 output stores are STG.128.
__global__ void __launch_bounds__(128, 3)
alphaC0_kernel(const float* __restrict__ alpha,
               const float* __restrict__ C0,
               float* __restrict__ out,
               int total_quads)
{
    __shared__ u64 c0s2[81];       // C0 value duplicated into both f32x2 lanes
    if (threadIdx.x < 81) c0s2[threadIdx.x] = f2dup(C0[threadIdx.x]);
    __syncthreads();

    const int tid = blockIdx.x * blockDim.x + threadIdx.x;
    if (tid >= total_quads) return;

    const int b = tid >> 16;                     // / QUADS_PER_B
    const int v = (tid & (QUADS_PER_B - 1)) * 4;

    // A4[m][i] = 4-voxel pack of alpha[b][m][i][v..v+3]
    Q A4[3][3];
#pragma unroll
    for (int m = 0; m < 3; m++)
#pragma unroll
        for (int i = 0; i < 3; i++)
            A4[m][i] = *reinterpret_cast<const Q*>(
                &alpha[(size_t)((b * 3 + m) * 3 + i) * G3 + v]);

    char* const outb0 = reinterpret_cast<char*>(out)
                      + ((size_t)b * 81 * G3 + v) * sizeof(float);

#pragma unroll 1
    for (int i = 0; i < 3; i++) {
        Q a0, a1, a2;
        if (i == 0)      { a0 = A4[0][0]; a1 = A4[1][0]; a2 = A4[2][0]; }
        else if (i == 1) { a0 = A4[0][1]; a1 = A4[1][1]; a2 = A4[2][1]; }
        else             { a0 = A4[0][2]; a1 = A4[1][2]; a2 = A4[2][2]; }

        // Fused stage1+2: T2[j][o][p] = sum_n A[n][j] * (sum_m a_m C0[m][n][o][p])
        Q T2[27];
#pragma unroll
        for (int o = 0; o < 3; o++) {
#pragma unroll
            for (int p = 0; p < 3; p++) {
                Q t1[3];
#pragma unroll
                for (int n = 0; n < 3; n++) {
                    t1[n] = qfmac(a0, c0s2[((0 * 3 + n) * 3 + o) * 3 + p],
                            qfmac(a1, c0s2[((1 * 3 + n) * 3 + o) * 3 + p],
                            qmulc(a2, c0s2[((2 * 3 + n) * 3 + o) * 3 + p])));
                }
#pragma unroll
                for (int j = 0; j < 3; j++) {
                    T2[(j * 3 + o) * 3 + p] =
                        qfma(A4[0][j], t1[0],
                        qfma(A4[1][j], t1[1],
                        qmul(A4[2][j], t1[2])));
                }
            }
        }

        // Fused stage3+4: per (j,k) build t3[p], emit 3 STG.128 immediately
        char* const outb = outb0 + (size_t)(i * 27) * G3 * sizeof(float);
#pragma unroll
        for (int j = 0; j < 3; j++) {
#pragma unroll
            for (int k = 0; k < 3; k++) {
                Q t3[3];
#pragma unroll
                for (int p = 0; p < 3; p++) {
                    t3[p] = qfma(A4[0][k], T2[(j * 3 + 0) * 3 + p],
                            qfma(A4[1][k], T2[(j * 3 + 1) * 3 + p],
                            qmul(A4[2][k], T2[(j * 3 + 2) * 3 + p])));
                }
#pragma unroll
                for (int l = 0; l < 3; l++) {
                    *reinterpret_cast<Q*>(
                        outb + (size_t)((j * 3 + k) * 3 + l) * G3 * sizeof(float)) =
                        qfma(A4[0][l], t3[0],
                        qfma(A4[1][l], t3[1],
                        qmul(A4[2][l], t3[2])));
                }
            }
        }
    }
}

extern "C" void kernel_launch(void* const* d_in, const int* in_sizes, int n_in,
                              void* d_out, int out_size)
{
    const float* alpha = (const float*)d_in[0];   // (B,3,3,G,G,G) float32
    const float* C0    = (const float*)d_in[1];   // (3,3,3,3) float32
    float* out         = (float*)d_out;           // (B,3,3,3,3,G,G,G) float32

    const int total_quads = in_sizes[0] / 36;     // B * G^3 / 4
    const int threads = 128;
    const int blocks = (total_quads + threads - 1) / threads;
    alphaC0_kernel<<<blocks, threads>>>(alpha, C0, out, total_quads);
}

// round 6
// speedup vs baseline: 1.5862x; 1.5862x over previous
#include <cuda_runtime.h>

#define G3 (64 * 64 * 64)          // 262144 voxels per batch
#define QUADS_PER_B (G3 / 4)       // 65536 voxel quads per batch

typedef unsigned long long u64;

__device__ __forceinline__ u64 f2fma(u64 a, u64 b, u64 c) {
    u64 d; asm("fma.rn.f32x2 %0, %1, %2, %3;" : "=l"(d) : "l"(a), "l"(b), "l"(c)); return d;
}
__device__ __forceinline__ u64 f2mul(u64 a, u64 b) {
    u64 d; asm("mul.rn.f32x2 %0, %1, %2;" : "=l"(d) : "l"(a), "l"(b)); return d;
}
__device__ __forceinline__ u64 f2dup(float x) {
    u64 d; asm("mov.b64 %0, {%1, %1};" : "=l"(d) : "f"(x)); return d;
}

// Quad value: 4 voxels = two f32x2 lanes; 16B aligned -> LDG.128 / STG.128.
struct __align__(16) Q { u64 x, y; };

__device__ __forceinline__ Q qfma(Q a, Q b, Q c) {
    Q r; r.x = f2fma(a.x, b.x, c.x); r.y = f2fma(a.y, b.y, c.y); return r;
}
__device__ __forceinline__ Q qmul(Q a, Q b) {
    Q r; r.x = f2mul(a.x, b.x); r.y = f2mul(a.y, b.y); return r;
}
__device__ __forceinline__ Q qfmac(Q a, u64 c0, Q c) {
    Q r; r.x = f2fma(a.x, c0, c.x); r.y = f2fma(a.y, c0, c.y); return r;
}
__device__ __forceinline__ Q qmulc(Q a, u64 c0) {
    Q r; r.x = f2mul(a.x, c0); r.y = f2mul(a.y, c0); return r;
}

// One thread = 4 consecutive voxels x ONE output index i (= blockIdx.y).
// Peak live state: T2 (27 quads, 108 regs) + A (9 quads, 36) + temps.
// launch_bounds(128,2) -> 255-reg cap: NO spills (R4's 170-cap spilled).
__global__ void __launch_bounds__(128, 2)
alphaC0_kernel(const float* __restrict__ alpha,
               const float* __restrict__ C0,
               float* __restrict__ out,
               int quads_total)
{
    __shared__ u64 c0s2[81];       // C0 duplicated into both f32x2 lanes
    if (threadIdx.x < 81) c0s2[threadIdx.x] = f2dup(C0[threadIdx.x]);
    __syncthreads();

    const int tid = blockIdx.x * blockDim.x + threadIdx.x;
    if (tid >= quads_total) return;

    const int i = blockIdx.y;                    // output index slice (0..2), warp-uniform
    const int b = tid >> 16;                     // / QUADS_PER_B
    const int v = (tid & (QUADS_PER_B - 1)) * 4;

    // A4[m][col] = 4-voxel pack of alpha[b][m][col][v..v+3]
    Q A4[3][3];
#pragma unroll
    for (int m = 0; m < 3; m++)
#pragma unroll
        for (int c = 0; c < 3; c++)
            A4[m][c] = *reinterpret_cast<const Q*>(
                &alpha[(size_t)((b * 3 + m) * 3 + c) * G3 + v]);

    // a_m = A4[m][i] via uniform branch (no dynamic register indexing)
    Q a0, a1, a2;
    if (i == 0)      { a0 = A4[0][0]; a1 = A4[1][0]; a2 = A4[2][0]; }
    else if (i == 1) { a0 = A4[0][1]; a1 = A4[1][1]; a2 = A4[2][1]; }
    else             { a0 = A4[0][2]; a1 = A4[1][2]; a2 = A4[2][2]; }

    // Fused stage1+2: T2[j][o][p] = sum_n A[n][j] * (sum_m a_m C0[m][n][o][p])
    Q T2[27];
#pragma unroll
    for (int o = 0; o < 3; o++) {
#pragma unroll
        for (int p = 0; p < 3; p++) {
            Q t1[3];
#pragma unroll
            for (int n = 0; n < 3; n++) {
                t1[n] = qfmac(a0, c0s2[((0 * 3 + n) * 3 + o) * 3 + p],
                        qfmac(a1, c0s2[((1 * 3 + n) * 3 + o) * 3 + p],
                        qmulc(a2, c0s2[((2 * 3 + n) * 3 + o) * 3 + p])));
            }
#pragma unroll
            for (int j = 0; j < 3; j++) {
                T2[(j * 3 + o) * 3 + p] =
                    qfma(A4[0][j], t1[0],
                    qfma(A4[1][j], t1[1],
                    qmul(A4[2][j], t1[2])));
            }
        }
    }

    // Fused stage3+4: per (j,k) build t3[p], emit 3 STG.128 immediately
    char* const outb = reinterpret_cast<char*>(out)
                     + ((size_t)(b * 81 + i * 27) * G3 + v) * sizeof(float);
#pragma unroll
    for (int j = 0; j < 3; j++) {
#pragma unroll
        for (int k = 0; k < 3; k++) {
            Q t3[3];
#pragma unroll
            for (int p = 0; p < 3; p++) {
                t3[p] = qfma(A4[0][k], T2[(j * 3 + 0) * 3 + p],
                        qfma(A4[1][k], T2[(j * 3 + 1) * 3 + p],
                        qmul(A4[2][k], T2[(j * 3 + 2) * 3 + p])));
            }
#pragma unroll
            for (int l = 0; l < 3; l++) {
                *reinterpret_cast<Q*>(
                    outb + (size_t)((j * 3 + k) * 3 + l) * G3 * sizeof(float)) =
                    qfma(A4[0][l], t3[0],
                    qfma(A4[1][l], t3[1],
                    qmul(A4[2][l], t3[2])));
            }
        }
    }
}

extern "C" void kernel_launch(void* const* d_in, const int* in_sizes, int n_in,
                              void* d_out, int out_size)
{
    const float* alpha = (const float*)d_in[0];   // (B,3,3,G,G,G) float32
    const float* C0    = (const float*)d_in[1];   // (3,3,3,3) float32
    float* out         = (float*)d_out;           // (B,3,3,3,3,G,G,G) float32

    const int quads_total = in_sizes[0] / 36;     // B * G^3 / 4
    const int threads = 128;
    dim3 grid((quads_total + threads - 1) / threads, 3, 1);  // y = output index i
    alphaC0_kernel<<<grid, threads>>>(alpha, C0, out, quads_total);
}